// round 10
// baseline (speedup 1.0000x reference)
#include <cuda_runtime.h>

#define NCODES 8192
#define DDIM   512
#define MROWS  32768
#define CHUNK  8                 // codes staged per smem chunk
#define RPW    4                 // rows per warp
#define WARPS  8                 // warps per block
#define RPB    (RPW * WARPS)     // 32 rows per block

// Transparent kernel (round-6 structure, unchanged math). Each warp owns 4
// consecutive x-rows in registers; the block streams the codebook through
// shared memory in 8-code chunks; argmin of (||c||^2 - 2 x.c) per row with
// ascending-index first-min semantics.
// ONLY change vs round 6: output is stored as float32 *values* — the six
// identical rel_err=1.0 failures (incl. a correct-by-inspection kernel) are
// explained by the harness treating d_out as float32: int codes 0..8191 are
// float32 denormals ~= 0 -> ||out-ref||/||ref|| = 1.0 exactly, every time.
__global__ __launch_bounds__(256) void vq_simple_kernel(
    const float* __restrict__ x, const float* __restrict__ cb,
    float* __restrict__ out)
{
    __shared__ float c_s[CHUNK * DDIM];   // 16 KB
    __shared__ float cn_s[CHUNK];

    const int tid  = threadIdx.x;
    const int lane = tid & 31;
    const int w    = tid >> 5;                            // warp id 0..7
    const int rowbase = blockIdx.x * RPB + w * RPW;       // first of 4 rows

    // x rows in registers: xr[r][j] = x[row_r][j*32 + lane]
    float xr[RPW][16];
#pragma unroll
    for (int r = 0; r < RPW; ++r)
#pragma unroll
        for (int j = 0; j < 16; ++j)
            xr[r][j] = x[(size_t)(rowbase + r) * DDIM + j * 32 + lane];

    float best[RPW];
    int   bidx[RPW];
#pragma unroll
    for (int r = 0; r < RPW; ++r) { best[r] = 3.4e38f; bidx[r] = 0; }

    for (int c0 = 0; c0 < NCODES; c0 += CHUNK) {
        __syncthreads();   // previous chunk fully consumed before overwrite
        // Stage CHUNK codes: plain linear copy, coalesced.
#pragma unroll
        for (int i = 0; i < (CHUNK * DDIM) / 256; ++i)    // 16 iters
            c_s[tid + i * 256] = cb[(size_t)c0 * DDIM + tid + i * 256];
        __syncthreads();

        // Warp w computes ||code w||^2 for this chunk.
        {
            float s = 0.f;
#pragma unroll
            for (int j = 0; j < 16; ++j) {
                float v = c_s[w * DDIM + j * 32 + lane];
                s = fmaf(v, v, s);
            }
#pragma unroll
            for (int o = 16; o > 0; o >>= 1)
                s += __shfl_down_sync(0xffffffffu, s, o);
            if (lane == 0) cn_s[w] = s;
        }
        __syncthreads();

#pragma unroll
        for (int c = 0; c < CHUNK; ++c) {
            float d0 = 0.f, d1 = 0.f, d2 = 0.f, d3 = 0.f;
#pragma unroll
            for (int j = 0; j < 16; ++j) {
                float v = c_s[c * DDIM + j * 32 + lane];   // conflict-free
                d0 = fmaf(xr[0][j], v, d0);
                d1 = fmaf(xr[1][j], v, d1);
                d2 = fmaf(xr[2][j], v, d2);
                d3 = fmaf(xr[3][j], v, d3);
            }
#pragma unroll
            for (int o = 16; o > 0; o >>= 1) {
                d0 += __shfl_down_sync(0xffffffffu, d0, o);
                d1 += __shfl_down_sync(0xffffffffu, d1, o);
                d2 += __shfl_down_sync(0xffffffffu, d2, o);
                d3 += __shfl_down_sync(0xffffffffu, d3, o);
            }
            if (lane == 0) {
                const float cn = cn_s[c];
                const int   ci = c0 + c;     // ascending => strict < keeps first min
                float d;
                d = fmaf(-2.f, d0, cn); if (d < best[0]) { best[0] = d; bidx[0] = ci; }
                d = fmaf(-2.f, d1, cn); if (d < best[1]) { best[1] = d; bidx[1] = ci; }
                d = fmaf(-2.f, d2, cn); if (d < best[2]) { best[2] = d; bidx[2] = ci; }
                d = fmaf(-2.f, d3, cn); if (d < best[3]) { best[3] = d; bidx[3] = ci; }
            }
        }
    }

    if (lane == 0) {
#pragma unroll
        for (int r = 0; r < RPW; ++r)
            out[rowbase + r] = (float)bidx[r];   // codes <= 8191: exact in fp32
    }
}

extern "C" void kernel_launch(void* const* d_in, const int* in_sizes, int n_in,
                              void* d_out, int out_size) {
    // x entry in in_sizes is strictly larger than codebook's under element- or
    // byte-units; select by size (robust to ordering).
    const float* p0 = (const float*)d_in[0];
    const float* p1 = (const float*)d_in[1];
    const float* x  = (in_sizes[0] > in_sizes[1]) ? p0 : p1;
    const float* cb = (in_sizes[0] > in_sizes[1]) ? p1 : p0;
    float* out = (float*)d_out;   // (8, 4096) as float32 values

    vq_simple_kernel<<<MROWS / RPB, 256>>>(x, cb, out);
}

// round 13
// speedup vs baseline: 1.3793x; 1.3793x over previous
#include <cuda_runtime.h>
#include <cuda_bf16.h>
#include <cstdint>

#define NCODES 8192
#define DDIM   512
#define MROWS  32768
#define NTERMS 6
#define KTOT   (NTERMS * DDIM)    // 3072
#define BM     128
#define BN     128
#define BK     32
#define KCHUNKS (KTOT / BK)       // 96
#define NPASS  (NCODES / BN)      // 64
#define LDS_PAD 40                // bf16 row stride (80 B) -> conflict-free ldmatrix

// Split scratch (device globals are the sanctioned scratch path)
__device__ __nv_bfloat16 g_xs[(size_t)MROWS * KTOT];    // 192 MB
__device__ __nv_bfloat16 g_cs[(size_t)NCODES * KTOT];   // 48 MB
__device__ float g_cnorm[NCODES];

__device__ __forceinline__ uint32_t smem_u32(const void* p) {
    uint32_t a;
    asm("{ .reg .u64 t; cvta.to.shared.u64 t, %1; cvt.u32.u64 %0, t; }" : "=r"(a) : "l"(p));
    return a;
}
__device__ __forceinline__ void ldsm_x4(uint32_t r[4], uint32_t addr) {
    asm volatile("ldmatrix.sync.aligned.m8n8.x4.shared.b16 {%0,%1,%2,%3}, [%4];"
        : "=r"(r[0]), "=r"(r[1]), "=r"(r[2]), "=r"(r[3]) : "r"(addr));
}
__device__ __forceinline__ void mma_bf16(float c[4], const uint32_t a[4], const uint32_t b[2]) {
    asm volatile("mma.sync.aligned.m16n8k16.row.col.f32.bf16.bf16.f32 "
        "{%0,%1,%2,%3}, {%4,%5,%6,%7}, {%8,%9}, {%0,%1,%2,%3};"
        : "+f"(c[0]), "+f"(c[1]), "+f"(c[2]), "+f"(c[3])
        : "r"(a[0]), "r"(a[1]), "r"(a[2]), "r"(a[3]), "r"(b[0]), "r"(b[1]));
}

// ---- precompute: 3-way bf16 split, 6-term cross-product packing ----
// x-seq blocks: [h, h, m, h, l, m] ; c-seq blocks: [h, m, h, l, h, m]
// => K-dot = xh*ch + xh*cm + xm*ch + xh*cl + xl*ch + xm*cm  (error ~2^-27 rel)
__global__ __launch_bounds__(256) void split_x_kernel(const float* __restrict__ src) {
    size_t i = (size_t)blockIdx.x * 256 + threadIdx.x;    // over MROWS*DDIM
    float v = src[i];
    __nv_bfloat16 h = __float2bfloat16(v);
    float r = v - __bfloat162float(h);
    __nv_bfloat16 m = __float2bfloat16(r);
    float r2 = r - __bfloat162float(m);
    __nv_bfloat16 l = __float2bfloat16(r2);
    size_t row = i / DDIM, col = i % DDIM;
    __nv_bfloat16* b = g_xs + row * KTOT + col;
    b[0 * DDIM] = h; b[1 * DDIM] = h; b[2 * DDIM] = m;
    b[3 * DDIM] = h; b[4 * DDIM] = l; b[5 * DDIM] = m;
}
__global__ __launch_bounds__(256) void split_c_kernel(const float* __restrict__ src) {
    size_t i = (size_t)blockIdx.x * 256 + threadIdx.x;    // over NCODES*DDIM
    float v = src[i];
    __nv_bfloat16 h = __float2bfloat16(v);
    float r = v - __bfloat162float(h);
    __nv_bfloat16 m = __float2bfloat16(r);
    float r2 = r - __bfloat162float(m);
    __nv_bfloat16 l = __float2bfloat16(r2);
    size_t row = i / DDIM, col = i % DDIM;
    __nv_bfloat16* b = g_cs + row * KTOT + col;
    b[0 * DDIM] = h; b[1 * DDIM] = m; b[2 * DDIM] = h;
    b[3 * DDIM] = l; b[4 * DDIM] = h; b[5 * DDIM] = m;
}
__global__ __launch_bounds__(256) void cnorm_kernel(const float* __restrict__ cb) {
    int code = blockIdx.x * 8 + (threadIdx.x >> 5);
    int lane = threadIdx.x & 31;
    const float4* row = reinterpret_cast<const float4*>(cb + (size_t)code * DDIM);
    float s = 0.f;
#pragma unroll
    for (int i = 0; i < 4; ++i) {
        float4 v = row[lane + i * 32];
        s += v.x * v.x + v.y * v.y + v.z * v.z + v.w * v.w;
    }
#pragma unroll
    for (int o = 16; o > 0; o >>= 1) s += __shfl_down_sync(0xffffffffu, s, o);
    if (lane == 0) g_cnorm[code] = s;
}

// ---- main: bf16 mma.sync GEMM (M=32768,N=8192,K=3072) + fused argmin ----
__global__ __launch_bounds__(256, 1) void vq_mma_kernel(float* __restrict__ out) {
    __shared__ __align__(16) __nv_bfloat16 a_s[BM * LDS_PAD];   // 10 KB
    __shared__ __align__(16) __nv_bfloat16 b_s[BN * LDS_PAD];   // 10 KB
    __shared__ float red_b[4][BM];
    __shared__ int   red_i[4][BM];

    const int tid  = threadIdx.x;
    const int lane = tid & 31;
    const int wid  = tid >> 5;
    const int warpM = wid >> 2;          // 0..1 : rows warpM*64..+63
    const int warpN = wid & 3;           // 0..3 : cols warpN*32..+31
    const int m0 = blockIdx.x * BM;

    const uint32_t a_base = smem_u32(a_s);
    const uint32_t b_base = smem_u32(b_s);

    // ldmatrix lane addressing (fixed for the whole kernel).
    // A (row-major [m][k]): non-trans, addressed by m-rows.
    // B ([n][k], k contiguous == col-major kxn): ALSO non-trans, addressed by
    // n-rows -> thread t gets B[k=2*(t%4)..+1][n=t/4], the exact b-fragment.
    const int sub = lane >> 3, lr = lane & 7;
    uint32_t a_addr[4][2], b_addr[2][2];
#pragma unroll
    for (int mt = 0; mt < 4; ++mt)
#pragma unroll
        for (int ks = 0; ks < 2; ++ks) {
            int row  = warpM * 64 + mt * 16 + ((sub & 1) << 3) + lr;
            int koff = ks * 16 + ((sub >> 1) << 3);
            a_addr[mt][ks] = a_base + (uint32_t)(row * LDS_PAD + koff) * 2;
        }
#pragma unroll
    for (int nt2 = 0; nt2 < 2; ++nt2)
#pragma unroll
        for (int ks = 0; ks < 2; ++ks) {
            int row  = warpN * 32 + nt2 * 16 + ((sub >> 1) << 3) + lr;
            int koff = ks * 16 + ((sub & 1) << 3);
            b_addr[nt2][ks] = b_base + (uint32_t)(row * LDS_PAD + koff) * 2;
        }

    // staging coords: thread covers rows ldrow & ldrow+64, 16-byte quad ldq
    const int ldrow = tid >> 2, ldq = tid & 3;
    const __nv_bfloat16* ax0 = g_xs + (size_t)(m0 + ldrow) * KTOT + ldq * 8;
    const __nv_bfloat16* ax1 = ax0 + (size_t)64 * KTOT;

    float best[8];
    int   bidx[8];
#pragma unroll
    for (int s = 0; s < 8; ++s) { best[s] = 3.4e38f; bidx[s] = 0; }

#pragma unroll 1
    for (int p = 0; p < NPASS; ++p) {
        const int n0 = p * BN;
        const __nv_bfloat16* bx0 = g_cs + (size_t)(n0 + ldrow) * KTOT + ldq * 8;
        const __nv_bfloat16* bx1 = bx0 + (size_t)64 * KTOT;

        float c[4][4][4];
#pragma unroll
        for (int mt = 0; mt < 4; ++mt)
#pragma unroll
            for (int nt = 0; nt < 4; ++nt)
#pragma unroll
                for (int k = 0; k < 4; ++k) c[mt][nt][k] = 0.f;

        // prefetch chunk 0
        uint4 pa0 = *reinterpret_cast<const uint4*>(ax0);
        uint4 pa1 = *reinterpret_cast<const uint4*>(ax1);
        uint4 pb0 = *reinterpret_cast<const uint4*>(bx0);
        uint4 pb1 = *reinterpret_cast<const uint4*>(bx1);

#pragma unroll 1
        for (int kc = 0; kc < KCHUNKS; ++kc) {
            __syncthreads();   // previous chunk consumed by all warps
            *reinterpret_cast<uint4*>(a_s + ldrow * LDS_PAD + ldq * 8) = pa0;
            *reinterpret_cast<uint4*>(a_s + (ldrow + 64) * LDS_PAD + ldq * 8) = pa1;
            *reinterpret_cast<uint4*>(b_s + ldrow * LDS_PAD + ldq * 8) = pb0;
            *reinterpret_cast<uint4*>(b_s + (ldrow + 64) * LDS_PAD + ldq * 8) = pb1;
            __syncthreads();

            if (kc + 1 < KCHUNKS) {
                int ko = (kc + 1) * BK;
                pa0 = *reinterpret_cast<const uint4*>(ax0 + ko);
                pa1 = *reinterpret_cast<const uint4*>(ax1 + ko);
                pb0 = *reinterpret_cast<const uint4*>(bx0 + ko);
                pb1 = *reinterpret_cast<const uint4*>(bx1 + ko);
            }

#pragma unroll
            for (int ks = 0; ks < 2; ++ks) {
                uint32_t af[4][4], bf[4][2];
#pragma unroll
                for (int mt = 0; mt < 4; ++mt) ldsm_x4(af[mt], a_addr[mt][ks]);
#pragma unroll
                for (int nt2 = 0; nt2 < 2; ++nt2) {
                    uint32_t r[4];
                    ldsm_x4(r, b_addr[nt2][ks]);   // non-trans (bug fix vs R12)
                    bf[nt2 * 2][0] = r[0]; bf[nt2 * 2][1] = r[1];
                    bf[nt2 * 2 + 1][0] = r[2]; bf[nt2 * 2 + 1][1] = r[3];
                }
#pragma unroll
                for (int mt = 0; mt < 4; ++mt)
#pragma unroll
                    for (int nt = 0; nt < 4; ++nt)
                        mma_bf16(c[mt][nt], af[mt], bf[nt]);
            }
        }

        // fused argmin epilogue: d = ||c||^2 - 2 x.c  (||x||^2 row-constant, dropped)
#pragma unroll
        for (int nt = 0; nt < 4; ++nt) {
            int col0 = n0 + warpN * 32 + nt * 8 + (lane & 3) * 2;
            float cn0 = __ldg(&g_cnorm[col0]);
            float cn1 = __ldg(&g_cnorm[col0 + 1]);
#pragma unroll
            for (int mt = 0; mt < 4; ++mt) {
                float d;
                d = fmaf(-2.f, c[mt][nt][0], cn0);
                if (d < best[mt * 2])     { best[mt * 2] = d;     bidx[mt * 2] = col0; }
                d = fmaf(-2.f, c[mt][nt][1], cn1);
                if (d < best[mt * 2])     { best[mt * 2] = d;     bidx[mt * 2] = col0 + 1; }
                d = fmaf(-2.f, c[mt][nt][2], cn0);
                if (d < best[mt * 2 + 1]) { best[mt * 2 + 1] = d; bidx[mt * 2 + 1] = col0; }
                d = fmaf(-2.f, c[mt][nt][3], cn1);
                if (d < best[mt * 2 + 1]) { best[mt * 2 + 1] = d; bidx[mt * 2 + 1] = col0 + 1; }
            }
        }
    }

    // quad reduce (4 lanes share each row), then cross-warpN via smem
#pragma unroll
    for (int s = 0; s < 8; ++s) {
        float bv = best[s]; int bi = bidx[s];
#pragma unroll
        for (int off = 1; off < 4; off <<= 1) {
            float ov = __shfl_down_sync(0xffffffffu, bv, off, 4);
            int   oi = __shfl_down_sync(0xffffffffu, bi, off, 4);
            if (ov < bv || (ov == bv && oi < bi)) { bv = ov; bi = oi; }
        }
        if ((lane & 3) == 0) {
            int row_l = warpM * 64 + (s >> 1) * 16 + (lane >> 2) + (s & 1) * 8;
            red_b[warpN][row_l] = bv;
            red_i[warpN][row_l] = bi;
        }
    }
    __syncthreads();
    if (tid < BM) {
        float bv = red_b[0][tid]; int bi = red_i[0][tid];
#pragma unroll
        for (int j = 1; j < 4; ++j) {
            float ov = red_b[j][tid]; int oi = red_i[j][tid];
            if (ov < bv || (ov == bv && oi < bi)) { bv = ov; bi = oi; }
        }
        out[m0 + tid] = (float)bi;   // codes <= 8191 exact in fp32
    }
}

extern "C" void kernel_launch(void* const* d_in, const int* in_sizes, int n_in,
                              void* d_out, int out_size) {
    const float* p0 = (const float*)d_in[0];
    const float* p1 = (const float*)d_in[1];
    const float* x  = (in_sizes[0] > in_sizes[1]) ? p0 : p1;  // larger = x
    const float* cb = (in_sizes[0] > in_sizes[1]) ? p1 : p0;
    float* out = (float*)d_out;

    split_x_kernel<<<(MROWS * DDIM) / 256, 256>>>(x);
    split_c_kernel<<<(NCODES * DDIM) / 256, 256>>>(cb);
    cnorm_kernel<<<NCODES / 8, 256>>>(cb);
    vq_mma_kernel<<<MROWS / BM, 256>>>(out);
}

// round 14
// speedup vs baseline: 1.4460x; 1.0483x over previous
#include <cuda_runtime.h>
#include <cuda_bf16.h>
#include <cstdint>

#define NCODES 8192
#define DDIM   512
#define MROWS  32768
#define NTERMS 6
#define KTOT   (NTERMS * DDIM)    // 3072
#define BM     128
#define BN     128
#define BK     32
#define KCHUNKS (KTOT / BK)       // 96
#define NPASS  (NCODES / BN)      // 64
#define LDS_PAD 40                // bf16 row stride (80 B) -> conflict-free ldmatrix, 16B-aligned rows

// Split scratch (device globals are the sanctioned scratch path)
__device__ __nv_bfloat16 g_xs[(size_t)MROWS * KTOT];    // 192 MB
__device__ __nv_bfloat16 g_cs[(size_t)NCODES * KTOT];   // 48 MB
__device__ float g_cnorm[NCODES];

__device__ __forceinline__ uint32_t smem_u32(const void* p) {
    uint32_t a;
    asm("{ .reg .u64 t; cvta.to.shared.u64 t, %1; cvt.u32.u64 %0, t; }" : "=r"(a) : "l"(p));
    return a;
}
__device__ __forceinline__ void ldsm_x4(uint32_t r[4], uint32_t addr) {
    asm volatile("ldmatrix.sync.aligned.m8n8.x4.shared.b16 {%0,%1,%2,%3}, [%4];"
        : "=r"(r[0]), "=r"(r[1]), "=r"(r[2]), "=r"(r[3]) : "r"(addr));
}
__device__ __forceinline__ void mma_bf16(float c[4], const uint32_t a[4], const uint32_t b[2]) {
    asm volatile("mma.sync.aligned.m16n8k16.row.col.f32.bf16.bf16.f32 "
        "{%0,%1,%2,%3}, {%4,%5,%6,%7}, {%8,%9}, {%0,%1,%2,%3};"
        : "+f"(c[0]), "+f"(c[1]), "+f"(c[2]), "+f"(c[3])
        : "r"(a[0]), "r"(a[1]), "r"(a[2]), "r"(a[3]), "r"(b[0]), "r"(b[1]));
}
#define CP_ASYNC16(dst, src) \
    asm volatile("cp.async.ca.shared.global [%0], [%1], 16;" :: "r"(dst), "l"(src))
#define CP_COMMIT() asm volatile("cp.async.commit_group;" ::: "memory")
#define CP_WAIT1()  asm volatile("cp.async.wait_group 1;" ::: "memory")

// ---- precompute: 3-way bf16 split, 6-term cross-product packing ----
// x-seq blocks: [h, h, m, h, l, m] ; c-seq blocks: [h, m, h, l, h, m]
// => K-dot = xh*ch + xh*cm + xm*ch + xh*cl + xl*ch + xm*cm  (error ~2^-27 rel)
__global__ __launch_bounds__(256) void split_x_kernel(const float* __restrict__ src) {
    size_t i = (size_t)blockIdx.x * 256 + threadIdx.x;    // over MROWS*DDIM
    float v = src[i];
    __nv_bfloat16 h = __float2bfloat16(v);
    float r = v - __bfloat162float(h);
    __nv_bfloat16 m = __float2bfloat16(r);
    float r2 = r - __bfloat162float(m);
    __nv_bfloat16 l = __float2bfloat16(r2);
    size_t row = i / DDIM, col = i % DDIM;
    __nv_bfloat16* b = g_xs + row * KTOT + col;
    b[0 * DDIM] = h; b[1 * DDIM] = h; b[2 * DDIM] = m;
    b[3 * DDIM] = h; b[4 * DDIM] = l; b[5 * DDIM] = m;
}
__global__ __launch_bounds__(256) void split_c_kernel(const float* __restrict__ src) {
    size_t i = (size_t)blockIdx.x * 256 + threadIdx.x;    // over NCODES*DDIM
    float v = src[i];
    __nv_bfloat16 h = __float2bfloat16(v);
    float r = v - __bfloat162float(h);
    __nv_bfloat16 m = __float2bfloat16(r);
    float r2 = r - __bfloat162float(m);
    __nv_bfloat16 l = __float2bfloat16(r2);
    size_t row = i / DDIM, col = i % DDIM;
    __nv_bfloat16* b = g_cs + row * KTOT + col;
    b[0 * DDIM] = h; b[1 * DDIM] = m; b[2 * DDIM] = h;
    b[3 * DDIM] = l; b[4 * DDIM] = h; b[5 * DDIM] = m;
}
__global__ __launch_bounds__(256) void cnorm_kernel(const float* __restrict__ cb) {
    int code = blockIdx.x * 8 + (threadIdx.x >> 5);
    int lane = threadIdx.x & 31;
    const float4* row = reinterpret_cast<const float4*>(cb + (size_t)code * DDIM);
    float s = 0.f;
#pragma unroll
    for (int i = 0; i < 4; ++i) {
        float4 v = row[lane + i * 32];
        s += v.x * v.x + v.y * v.y + v.z * v.z + v.w * v.w;
    }
#pragma unroll
    for (int o = 16; o > 0; o >>= 1) s += __shfl_down_sync(0xffffffffu, s, o);
    if (lane == 0) g_cnorm[code] = s;
}

// ---- main: bf16 mma.sync GEMM (M=32768,N=8192,K=3072) + fused argmin ----
// Double-buffered cp.async pipeline, 2 CTAs/SM.
__global__ __launch_bounds__(256, 2) void vq_mma_kernel(float* __restrict__ out) {
    __shared__ __align__(16) __nv_bfloat16 a_s[2][BM * LDS_PAD];   // 2 x 10 KB
    __shared__ __align__(16) __nv_bfloat16 b_s[2][BN * LDS_PAD];   // 2 x 10 KB
    __shared__ float red_b[4][BM];
    __shared__ int   red_i[4][BM];

    const int tid  = threadIdx.x;
    const int lane = tid & 31;
    const int wid  = tid >> 5;
    const int warpM = wid >> 2;          // 0..1 : rows warpM*64..+63
    const int warpN = wid & 3;           // 0..3 : cols warpN*32..+31
    const int m0 = blockIdx.x * BM;

    // ldmatrix lane addressing. A: row-major [m][k] non-trans by m-rows.
    // B: [n][k] (k contiguous == col-major kxn) non-trans by n-rows.
    const int sub = lane >> 3, lr = lane & 7;
    uint32_t a_addr[2][4][2], b_addr[2][2][2];
#pragma unroll
    for (int bufi = 0; bufi < 2; ++bufi) {
        const uint32_t ab = smem_u32(a_s[bufi]);
        const uint32_t bb = smem_u32(b_s[bufi]);
#pragma unroll
        for (int mt = 0; mt < 4; ++mt)
#pragma unroll
            for (int ks = 0; ks < 2; ++ks) {
                int row  = warpM * 64 + mt * 16 + ((sub & 1) << 3) + lr;
                int koff = ks * 16 + ((sub >> 1) << 3);
                a_addr[bufi][mt][ks] = ab + (uint32_t)(row * LDS_PAD + koff) * 2;
            }
#pragma unroll
        for (int nt2 = 0; nt2 < 2; ++nt2)
#pragma unroll
            for (int ks = 0; ks < 2; ++ks) {
                int row  = warpN * 32 + nt2 * 16 + ((sub >> 1) << 3) + lr;
                int koff = ks * 16 + ((sub & 1) << 3);
                b_addr[bufi][nt2][ks] = bb + (uint32_t)(row * LDS_PAD + koff) * 2;
            }
    }

    // staging coords: thread covers rows ldrow & ldrow+64, 16-byte quad ldq
    const int ldrow = tid >> 2, ldq = tid & 3;
    const uint32_t sts_off = (uint32_t)(ldrow * LDS_PAD + ldq * 8) * 2;       // bytes
    const uint32_t sts_off64 = (uint32_t)((ldrow + 64) * LDS_PAD + ldq * 8) * 2;
    uint32_t a_sts[2], b_sts[2];
#pragma unroll
    for (int bufi = 0; bufi < 2; ++bufi) {
        a_sts[bufi] = smem_u32(a_s[bufi]);
        b_sts[bufi] = smem_u32(b_s[bufi]);
    }
    const __nv_bfloat16* ax0 = g_xs + (size_t)(m0 + ldrow) * KTOT + ldq * 8;
    const __nv_bfloat16* ax1 = ax0 + (size_t)64 * KTOT;

    float best[8];
    int   bidx[8];
#pragma unroll
    for (int s = 0; s < 8; ++s) { best[s] = 3.4e38f; bidx[s] = 0; }

#pragma unroll 1
    for (int p = 0; p < NPASS; ++p) {
        const int n0 = p * BN;
        const __nv_bfloat16* bx0 = g_cs + (size_t)(n0 + ldrow) * KTOT + ldq * 8;
        const __nv_bfloat16* bx1 = bx0 + (size_t)64 * KTOT;

        float c[4][4][4];
#pragma unroll
        for (int mt = 0; mt < 4; ++mt)
#pragma unroll
            for (int nt = 0; nt < 4; ++nt)
#pragma unroll
                for (int k = 0; k < 4; ++k) c[mt][nt][k] = 0.f;

        // prologue: stage chunk 0 into buffer 0
        CP_ASYNC16(a_sts[0] + sts_off,   (const char*)ax0);
        CP_ASYNC16(a_sts[0] + sts_off64, (const char*)ax1);
        CP_ASYNC16(b_sts[0] + sts_off,   (const char*)bx0);
        CP_ASYNC16(b_sts[0] + sts_off64, (const char*)bx1);
        CP_COMMIT();

#pragma unroll 1
        for (int kc = 0; kc < KCHUNKS; ++kc) {
            const int buf = kc & 1;
            // stage next chunk into the other buffer (overlaps with compute)
            if (kc + 1 < KCHUNKS) {
                const int nb = buf ^ 1;
                const int ko = (kc + 1) * BK;
                CP_ASYNC16(a_sts[nb] + sts_off,   (const char*)(ax0 + ko));
                CP_ASYNC16(a_sts[nb] + sts_off64, (const char*)(ax1 + ko));
                CP_ASYNC16(b_sts[nb] + sts_off,   (const char*)(bx0 + ko));
                CP_ASYNC16(b_sts[nb] + sts_off64, (const char*)(bx1 + ko));
            }
            CP_COMMIT();                  // always commit: group bookkeeping stays uniform
            CP_WAIT1();                   // chunk kc resident (newest group may be in flight)
            __syncthreads();

#pragma unroll
            for (int ks = 0; ks < 2; ++ks) {
                uint32_t af[4][4], bf[4][2];
#pragma unroll
                for (int mt = 0; mt < 4; ++mt) ldsm_x4(af[mt], a_addr[buf][mt][ks]);
#pragma unroll
                for (int nt2 = 0; nt2 < 2; ++nt2) {
                    uint32_t r[4];
                    ldsm_x4(r, b_addr[buf][nt2][ks]);
                    bf[nt2 * 2][0] = r[0]; bf[nt2 * 2][1] = r[1];
                    bf[nt2 * 2 + 1][0] = r[2]; bf[nt2 * 2 + 1][1] = r[3];
                }
#pragma unroll
                for (int mt = 0; mt < 4; ++mt)
#pragma unroll
                    for (int nt = 0; nt < 4; ++nt)
                        mma_bf16(c[mt][nt], af[mt], bf[nt]);
            }
            __syncthreads();              // all warps done with buf before it's re-staged
        }

        // fused argmin epilogue: d = ||c||^2 - 2 x.c  (||x||^2 row-constant, dropped)
#pragma unroll
        for (int nt = 0; nt < 4; ++nt) {
            int col0 = n0 + warpN * 32 + nt * 8 + (lane & 3) * 2;
            float cn0 = __ldg(&g_cnorm[col0]);
            float cn1 = __ldg(&g_cnorm[col0 + 1]);
#pragma unroll
            for (int mt = 0; mt < 4; ++mt) {
                float d;
                d = fmaf(-2.f, c[mt][nt][0], cn0);
                if (d < best[mt * 2])     { best[mt * 2] = d;     bidx[mt * 2] = col0; }
                d = fmaf(-2.f, c[mt][nt][1], cn1);
                if (d < best[mt * 2])     { best[mt * 2] = d;     bidx[mt * 2] = col0 + 1; }
                d = fmaf(-2.f, c[mt][nt][2], cn0);
                if (d < best[mt * 2 + 1]) { best[mt * 2 + 1] = d; bidx[mt * 2 + 1] = col0; }
                d = fmaf(-2.f, c[mt][nt][3], cn1);
                if (d < best[mt * 2 + 1]) { best[mt * 2 + 1] = d; bidx[mt * 2 + 1] = col0 + 1; }
            }
        }
    }

    // quad reduce (4 lanes share each row), then cross-warpN via smem
#pragma unroll
    for (int s = 0; s < 8; ++s) {
        float bv = best[s]; int bi = bidx[s];
#pragma unroll
        for (int off = 1; off < 4; off <<= 1) {
            float ov = __shfl_down_sync(0xffffffffu, bv, off, 4);
            int   oi = __shfl_down_sync(0xffffffffu, bi, off, 4);
            if (ov < bv || (ov == bv && oi < bi)) { bv = ov; bi = oi; }
        }
        if ((lane & 3) == 0) {
            int row_l = warpM * 64 + (s >> 1) * 16 + (lane >> 2) + (s & 1) * 8;
            red_b[warpN][row_l] = bv;
            red_i[warpN][row_l] = bi;
        }
    }
    __syncthreads();
    if (tid < BM) {
        float bv = red_b[0][tid]; int bi = red_i[0][tid];
#pragma unroll
        for (int j = 1; j < 4; ++j) {
            float ov = red_b[j][tid]; int oi = red_i[j][tid];
            if (ov < bv || (ov == bv && oi < bi)) { bv = ov; bi = oi; }
        }
        out[m0 + tid] = (float)bi;   // codes <= 8191 exact in fp32
    }
}

extern "C" void kernel_launch(void* const* d_in, const int* in_sizes, int n_in,
                              void* d_out, int out_size) {
    const float* p0 = (const float*)d_in[0];
    const float* p1 = (const float*)d_in[1];
    const float* x  = (in_sizes[0] > in_sizes[1]) ? p0 : p1;  // larger = x
    const float* cb = (in_sizes[0] > in_sizes[1]) ? p1 : p0;
    float* out = (float*)d_out;

    split_x_kernel<<<(MROWS * DDIM) / 256, 256>>>(x);
    split_c_kernel<<<(NCODES * DDIM) / 256, 256>>>(cb);
    cnorm_kernel<<<NCODES / 8, 256>>>(cb);
    vq_mma_kernel<<<MROWS / BM, 256>>>(out);
}

// round 16
// speedup vs baseline: 3.2883x; 2.2741x over previous
#include <cuda_runtime.h>
#include <cuda_fp16.h>
#include <cstdint>

#define NCODES 8192
#define DDIM   512
#define MROWS  32768
#define NTERMS 4
#define KTOT   (NTERMS * DDIM)    // 2048 fp16
#define BM     128
#define BN     128
#define BK     32
#define KCHUNKS (KTOT / BK)       // 64
#define NPASS  (NCODES / BN)      // 64
#define LDS_PAD 40                // half row stride (80 B): conflict-free ldmatrix, 16B-aligned
#define STAGES 4
#define ABYTES (BM * LDS_PAD * 2) // 10240
#define BBYTES (BN * LDS_PAD * 2) // 10240
#define STAGE_BYTES (ABYTES + BBYTES)          // 20480
#define DYN_SMEM (STAGES * STAGE_BYTES)        // 81920

// Split scratch (device globals are the sanctioned scratch path)
__device__ __half g_xs[(size_t)MROWS * KTOT];   // 128 MB
__device__ __half g_cs[(size_t)NCODES * KTOT];  // 32 MB
__device__ float g_cnorm[NCODES];

__device__ __forceinline__ uint32_t smem_u32(const void* p) {
    uint32_t a;
    asm("{ .reg .u64 t; cvta.to.shared.u64 t, %1; cvt.u32.u64 %0, t; }" : "=r"(a) : "l"(p));
    return a;
}
__device__ __forceinline__ void ldsm_x4(uint32_t r[4], uint32_t addr) {
    asm volatile("ldmatrix.sync.aligned.m8n8.x4.shared.b16 {%0,%1,%2,%3}, [%4];"
        : "=r"(r[0]), "=r"(r[1]), "=r"(r[2]), "=r"(r[3]) : "r"(addr));
}
__device__ __forceinline__ void mma_f16(float c[4], const uint32_t a[4], const uint32_t b[2]) {
    asm volatile("mma.sync.aligned.m16n8k16.row.col.f32.f16.f16.f32 "
        "{%0,%1,%2,%3}, {%4,%5,%6,%7}, {%8,%9}, {%0,%1,%2,%3};"
        : "+f"(c[0]), "+f"(c[1]), "+f"(c[2]), "+f"(c[3])
        : "r"(a[0]), "r"(a[1]), "r"(a[2]), "r"(a[3]), "r"(b[0]), "r"(b[1]));
}
#define CP_ASYNC16(dst, src) \
    asm volatile("cp.async.ca.shared.global [%0], [%1], 16;" :: "r"(dst), "l"(src))
#define CP_COMMIT() asm volatile("cp.async.commit_group;" ::: "memory")
#define CP_WAIT2()  asm volatile("cp.async.wait_group 2;" ::: "memory")

// ---- precompute: 2-way fp16 split, 4-term exact product packing ----
// x-seq [h, h, m, m] ; c-seq [h, m, h, m]  =>  K-dot = (xh+xm)(ch+cm) per elem,
// and xh+xm == x to ~2^-24 rel (fp32-equivalent).
__global__ __launch_bounds__(256) void split_x_kernel(const float* __restrict__ src) {
    size_t i = (size_t)blockIdx.x * 256 + threadIdx.x;    // over MROWS*DDIM
    float v = src[i];
    __half h = __float2half_rn(v);
    __half m = __float2half_rn(v - __half2float(h));
    size_t row = i / DDIM, col = i % DDIM;
    __half* b = g_xs + row * KTOT + col;
    b[0 * DDIM] = h; b[1 * DDIM] = h; b[2 * DDIM] = m; b[3 * DDIM] = m;
}
__global__ __launch_bounds__(256) void split_c_kernel(const float* __restrict__ src) {
    size_t i = (size_t)blockIdx.x * 256 + threadIdx.x;    // over NCODES*DDIM
    float v = src[i];
    __half h = __float2half_rn(v);
    __half m = __float2half_rn(v - __half2float(h));
    size_t row = i / DDIM, col = i % DDIM;
    __half* b = g_cs + row * KTOT + col;
    b[0 * DDIM] = h; b[1 * DDIM] = m; b[2 * DDIM] = h; b[3 * DDIM] = m;
}
__global__ __launch_bounds__(256) void cnorm_kernel(const float* __restrict__ cb) {
    int code = blockIdx.x * 8 + (threadIdx.x >> 5);
    int lane = threadIdx.x & 31;
    const float4* row = reinterpret_cast<const float4*>(cb + (size_t)code * DDIM);
    float s = 0.f;
#pragma unroll
    for (int i = 0; i < 4; ++i) {
        float4 v = row[lane + i * 32];
        s += v.x * v.x + v.y * v.y + v.z * v.z + v.w * v.w;
    }
#pragma unroll
    for (int o = 16; o > 0; o >>= 1) s += __shfl_down_sync(0xffffffffu, s, o);
    if (lane == 0) g_cnorm[code] = s;
}

// ---- main: fp16 mma.sync GEMM (M=32768,N=8192,K=2048) + fused argmin ----
// 4-stage cp.async pipeline, one barrier per K-chunk, 2 CTAs/SM.
__global__ __launch_bounds__(256, 2) void vq_mma_kernel(float* __restrict__ out) {
    extern __shared__ __align__(16) char dyn_s[];          // STAGES x (A | B)
    __shared__ float red_b[4][BM];
    __shared__ int   red_i[4][BM];

    const int tid  = threadIdx.x;
    const int lane = tid & 31;
    const int wid  = tid >> 5;
    const int warpM = wid >> 2;          // 0..1 : rows warpM*64..+63
    const int warpN = wid & 3;           // 0..3 : cols warpN*32..+31
    const int m0 = blockIdx.x * BM;
    const uint32_t sbase = smem_u32(dyn_s);

    // ldmatrix lane addressing (stage-0 addresses; add stage*STAGE_BYTES).
    // A: row-major [m][k] non-trans by m-rows. B: [n][k] non-trans by n-rows.
    const int sub = lane >> 3, lr = lane & 7;
    uint32_t a_addr[4][2], b_addr[2][2];
#pragma unroll
    for (int mt = 0; mt < 4; ++mt)
#pragma unroll
        for (int ks = 0; ks < 2; ++ks) {
            int row  = warpM * 64 + mt * 16 + ((sub & 1) << 3) + lr;
            int koff = ks * 16 + ((sub >> 1) << 3);
            a_addr[mt][ks] = sbase + (uint32_t)(row * LDS_PAD + koff) * 2;
        }
#pragma unroll
    for (int nt2 = 0; nt2 < 2; ++nt2)
#pragma unroll
        for (int ks = 0; ks < 2; ++ks) {
            int row  = warpN * 32 + nt2 * 16 + ((sub >> 1) << 3) + lr;
            int koff = ks * 16 + ((sub & 1) << 3);
            b_addr[nt2][ks] = sbase + ABYTES + (uint32_t)(row * LDS_PAD + koff) * 2;
        }

    // staging coords: thread covers rows ldrow & ldrow+64, 16-byte quad ldq
    const int ldrow = tid >> 2, ldq = tid & 3;
    const uint32_t a_st0 = sbase + (uint32_t)(ldrow * LDS_PAD + ldq * 8) * 2;
    const uint32_t a_st1 = sbase + (uint32_t)((ldrow + 64) * LDS_PAD + ldq * 8) * 2;
    const uint32_t b_st0 = a_st0 + ABYTES;
    const uint32_t b_st1 = a_st1 + ABYTES;
    const __half* ax0 = g_xs + (size_t)(m0 + ldrow) * KTOT + ldq * 8;
    const __half* ax1 = ax0 + (size_t)64 * KTOT;

    float best[8];
    int   bidx[8];
#pragma unroll
    for (int s = 0; s < 8; ++s) { best[s] = 3.4e38f; bidx[s] = 0; }

#pragma unroll 1
    for (int p = 0; p < NPASS; ++p) {
        const int n0 = p * BN;
        const __half* bx0 = g_cs + (size_t)(n0 + ldrow) * KTOT + ldq * 8;
        const __half* bx1 = bx0 + (size_t)64 * KTOT;

        float c[4][4][4];
#pragma unroll
        for (int mt = 0; mt < 4; ++mt)
#pragma unroll
            for (int nt = 0; nt < 4; ++nt)
#pragma unroll
                for (int k = 0; k < 4; ++k) c[mt][nt][k] = 0.f;

        // prologue: stage chunks 0..2 into slots 0..2
#pragma unroll
        for (int s = 0; s < STAGES - 1; ++s) {
            const uint32_t so = s * STAGE_BYTES;
            const int ko = s * BK;
            CP_ASYNC16(a_st0 + so, (const char*)(ax0 + ko));
            CP_ASYNC16(a_st1 + so, (const char*)(ax1 + ko));
            CP_ASYNC16(b_st0 + so, (const char*)(bx0 + ko));
            CP_ASYNC16(b_st1 + so, (const char*)(bx1 + ko));
            CP_COMMIT();
        }

#pragma unroll 1
        for (int kc = 0; kc < KCHUNKS; ++kc) {
            CP_WAIT2();                 // chunk kc resident (<=2 newer in flight)
            __syncthreads();            // ONE barrier per chunk
            // stage kc+3 into slot (kc+3)%4 == (kc-1)%4 (safe: barrier above)
            if (kc + STAGES - 1 < KCHUNKS) {
                const uint32_t so = ((kc + STAGES - 1) % STAGES) * STAGE_BYTES;
                const int ko = (kc + STAGES - 1) * BK;
                CP_ASYNC16(a_st0 + so, (const char*)(ax0 + ko));
                CP_ASYNC16(a_st1 + so, (const char*)(ax1 + ko));
                CP_ASYNC16(b_st0 + so, (const char*)(bx0 + ko));
                CP_ASYNC16(b_st1 + so, (const char*)(bx1 + ko));
            }
            CP_COMMIT();                // uniform group bookkeeping

            const uint32_t so = (kc % STAGES) * STAGE_BYTES;
#pragma unroll
            for (int ks = 0; ks < 2; ++ks) {
                uint32_t af[4][4], bf[4][2];
#pragma unroll
                for (int mt = 0; mt < 4; ++mt) ldsm_x4(af[mt], a_addr[mt][ks] + so);
#pragma unroll
                for (int nt2 = 0; nt2 < 2; ++nt2) {
                    uint32_t r[4];
                    ldsm_x4(r, b_addr[nt2][ks] + so);
                    bf[nt2 * 2][0] = r[0]; bf[nt2 * 2][1] = r[1];
                    bf[nt2 * 2 + 1][0] = r[2]; bf[nt2 * 2 + 1][1] = r[3];
                }
#pragma unroll
                for (int mt = 0; mt < 4; ++mt)
#pragma unroll
                    for (int nt = 0; nt < 4; ++nt)
                        mma_f16(c[mt][nt], af[mt], bf[nt]);
            }
        }

        // fused argmin epilogue: d = ||c||^2 - 2 x.c  (||x||^2 row-constant, dropped)
#pragma unroll
        for (int nt = 0; nt < 4; ++nt) {
            int col0 = n0 + warpN * 32 + nt * 8 + (lane & 3) * 2;
            float cn0 = __ldg(&g_cnorm[col0]);
            float cn1 = __ldg(&g_cnorm[col0 + 1]);
#pragma unroll
            for (int mt = 0; mt < 4; ++mt) {
                float d;
                d = fmaf(-2.f, c[mt][nt][0], cn0);
                if (d < best[mt * 2])     { best[mt * 2] = d;     bidx[mt * 2] = col0; }
                d = fmaf(-2.f, c[mt][nt][1], cn1);
                if (d < best[mt * 2])     { best[mt * 2] = d;     bidx[mt * 2] = col0 + 1; }
                d = fmaf(-2.f, c[mt][nt][2], cn0);
                if (d < best[mt * 2 + 1]) { best[mt * 2 + 1] = d; bidx[mt * 2 + 1] = col0; }
                d = fmaf(-2.f, c[mt][nt][3], cn1);
                if (d < best[mt * 2 + 1]) { best[mt * 2 + 1] = d; bidx[mt * 2 + 1] = col0 + 1; }
            }
        }
    }

    // quad reduce (4 lanes share each row), then cross-warpN via smem
#pragma unroll
    for (int s = 0; s < 8; ++s) {
        float bv = best[s]; int bi = bidx[s];
#pragma unroll
        for (int off = 1; off < 4; off <<= 1) {
            float ov = __shfl_down_sync(0xffffffffu, bv, off, 4);
            int   oi = __shfl_down_sync(0xffffffffu, bi, off, 4);
            if (ov < bv || (ov == bv && oi < bi)) { bv = ov; bi = oi; }
        }
        if ((lane & 3) == 0) {
            int row_l = warpM * 64 + (s >> 1) * 16 + (lane >> 2) + (s & 1) * 8;
            red_b[warpN][row_l] = bv;
            red_i[warpN][row_l] = bi;
        }
    }
    __syncthreads();
    if (tid < BM) {
        float bv = red_b[0][tid]; int bi = red_i[0][tid];
#pragma unroll
        for (int j = 1; j < 4; ++j) {
            float ov = red_b[j][tid]; int oi = red_i[j][tid];
            if (ov < bv || (ov == bv && oi < bi)) { bv = ov; bi = oi; }
        }
        out[m0 + tid] = (float)bi;   // codes <= 8191 exact in fp32
    }
}

extern "C" void kernel_launch(void* const* d_in, const int* in_sizes, int n_in,
                              void* d_out, int out_size) {
    const float* p0 = (const float*)d_in[0];
    const float* p1 = (const float*)d_in[1];
    const float* x  = (in_sizes[0] > in_sizes[1]) ? p0 : p1;  // larger = x
    const float* cb = (in_sizes[0] > in_sizes[1]) ? p1 : p0;
    float* out = (float*)d_out;

    cudaFuncSetAttribute(vq_mma_kernel, cudaFuncAttributeMaxDynamicSharedMemorySize, DYN_SMEM);

    split_x_kernel<<<(MROWS * DDIM) / 256, 256>>>(x);
    split_c_kernel<<<(NCODES * DDIM) / 256, 256>>>(cb);
    cnorm_kernel<<<NCODES / 8, 256>>>(cb);
    vq_mma_kernel<<<MROWS / BM, 256, DYN_SMEM>>>(out);
}